// round 9
// baseline (speedup 1.0000x reference)
#include <cuda_runtime.h>
#include <cuda_fp16.h>
#include <cstdint>
#include <math.h>

#define DEVI __device__ __forceinline__

static constexpr int BN = 16384, FAN = 16, BE = BN * FAN, EMB = 128, HID = 256;
static constexpr int NJOB = BE / 128;        // 2048 M-tiles
static constexpr int NSM  = 148;

// ---- device scratch (static; no allocations allowed) ----
__device__ __align__(16) float  g_relb2[16 * HID];
__device__ __align__(16) __half g_neighh[BN * HID];        // fp16, pair-permuted per 64-col block
__device__ __align__(16) __half g_Bwh [8 * 256 * 64];      // k_events B: fp16 swizzled smem image
__device__ __align__(16) __half g_Bw2h[6 * 256 * 64];      // k_final  B: same

DEVI uint32_t smaddr(const void* p) {
    uint32_t a;
    asm("{ .reg .u64 t; cvta.to.shared.u64 t, %1; cvt.u32.u64 %0, t; }" : "=r"(a) : "l"(p));
    return a;
}
DEVI void cpa16(uint32_t d, const void* s) {
    asm volatile("cp.async.ca.shared.global [%0], [%1], 16;" :: "r"(d), "l"(s));
}
#define CP_COMMIT() asm volatile("cp.async.commit_group;")
#define CP_WAIT(n)  asm volatile("cp.async.wait_group %0;" :: "n"(n))

DEVI void lds64(uint32_t& x, uint32_t& y, uint32_t a) {
    asm volatile("ld.shared.v2.b32 {%0,%1}, [%2];" : "=r"(x), "=r"(y) : "r"(a));
}
DEVI void sts128(uint32_t a, uint32_t x, uint32_t y, uint32_t z, uint32_t w) {
    asm volatile("st.shared.v4.b32 [%0], {%1,%2,%3,%4};" :: "r"(a), "r"(x), "r"(y), "r"(z), "r"(w) : "memory");
}
DEVI uint32_t h2u(__half2 h) { return *(uint32_t*)&h; }

// fp16 m16n8k16, fp32 accumulate
DEVI void mma16(float* c, const uint32_t* a, uint32_t b0, uint32_t b1) {
    asm volatile(
        "mma.sync.aligned.m16n8k16.row.col.f32.f16.f16.f32 "
        "{%0,%1,%2,%3}, {%4,%5,%6,%7}, {%8,%9}, {%0,%1,%2,%3};"
        : "+f"(c[0]), "+f"(c[1]), "+f"(c[2]), "+f"(c[3])
        : "r"(a[0]), "r"(a[1]), "r"(a[2]), "r"(a[3]), "r"(b0), "r"(b1));
}

// ---- fp16 smem image: row r (128B = 64 half), kstep ks, pair j ----
DEVI void stashh(__half* dst, int r, int k, float v) {
    int q = k >> 1, ks = q >> 3, j = q & 7;
    int p = 2 * (j & 3) + (j >> 2);
    int s8 = (ks * 4 + (p >> 1)) ^ ((r & 3) << 2);
    dst[r * 64 + s8 * 4 + (p & 1) * 2 + (k & 1)] = __float2half_rn(v);
}

// ================= k_events: B-stationary persistent kernel =================
// smem: Bres 8 chunks x 128 rows x 128B = 131072 | A 2 x 16384 | meta
static constexpr int EV_B    = 0;
static constexpr int EV_A    = 131072;
static constexpr int EV_META = EV_A + 32768;          // byte 163840
static constexpr int MJ      = EV_META / 4;           // float index 40960
static constexpr int MJ_SRCP = MJ;                     // 128 ptrs (256 f)
static constexpr int MJ_DSTP = MJ + 256;
static constexpr int MJ_REL  = MJ + 512;               // 128 int
static constexpr int MJ_VM   = MJ + 640;
static constexpr int MJ_TS   = MJ + 768;
static constexpr int MJ_WL   = MJ + 896;
static constexpr int MJ_W1   = MJ + 1024;              // 256 float2
static constexpr int MJ_B1   = MJ + 1536;              // 256 f
static constexpr int MJ_RB   = MJ + 1792;              // 16 x 128
static constexpr int SMEM_EV = (MJ_RB + 2048) * 4;     // 179200 B

// ---- legacy (k_final) constants ----
static constexpr int A_BYT  = 128 * 128;
static constexpr int B_BYT  = 256 * 128;
static constexpr int STG    = A_BYT + B_BYT;
static constexpr int CH_BYT = 256 * 64 * 2;
static constexpr int MI     = 3 * STG / 4;
static constexpr int SMEM_FI = (MI + 256) * 4;

// ---------------- kernel 0: stage weights (fp16 rn + permute + swizzle) ----------------
__global__ void k_prep(const float* __restrict__ Ws, const float* __restrict__ Wd,
                       const float* __restrict__ W2, const float* __restrict__ Wself,
                       const float* __restrict__ Wneigh) {
    int flat = blockIdx.x * 256 + threadIdx.x;
    if (flat < 8 * 16384) {
        int chunk = flat >> 14, r = (flat >> 6) & 255, k = flat & 63;
        float v;
        if (chunk < 2)      v = Ws[r * 128 + chunk * 64 + k];
        else if (chunk < 4) v = Wd[r * 128 + (chunk - 2) * 64 + k];
        else                v = W2[r * 256 + (chunk - 4) * 64 + k];
        stashh(g_Bwh + chunk * 16384, r, k, v);
    } else {
        int f = flat - 8 * 16384;
        int chunk = f >> 14, r = (f >> 6) & 255, k = f & 63;
        float v = (chunk < 2) ? Wself[r * 128 + chunk * 64 + k]
                              : Wneigh[r * 256 + (chunk - 2) * 64 + k];
        stashh(g_Bw2h + chunk * 16384, r, k, v);
    }
}

// ---------------- kernel 1: relb2 ----------------
__global__ void k_relproj(const float* __restrict__ eemb, const float* __restrict__ We,
                          const float* __restrict__ b2) {
    int r = blockIdx.x, j = threadIdx.x;
    const float4* e = (const float4*)(eemb + r * EMB);
    const float4* w = (const float4*)(We + (long)j * EMB);
    float acc = b2[j];
#pragma unroll
    for (int k = 0; k < EMB / 4; k++) {
        float4 a = e[k], b = w[k];
        acc += a.x * b.x + a.y * b.y + a.z * b.z + a.w * b.w;
    }
    g_relb2[r * HID + j] = acc;
}

extern __shared__ float smf[];

// convert 16 f32 (float4[4]) into permuted half2 image regs
DEVI void cvt_perm(const float4 (&f)[4], uint32_t (&h)[8]) {
#pragma unroll
    for (int p = 0; p < 8; p++) {
        int j = (p >> 1) + ((p & 1) << 2);
        float x = (j & 1) ? f[j >> 1].z : f[j >> 1].x;
        float y = (j & 1) ? f[j >> 1].w : f[j >> 1].y;
        h[p] = h2u(__floats2half2_rn(x, y));
    }
}

// per-kstep fragment load: warp tile 32x32 (2 m16 x 4 n8)
DEVI void frag32(uint32_t arow, uint32_t brow, uint32_t asw, int t, int ks,
                 uint32_t (&a)[2][4], uint32_t (&b)[4][2]) {
    const uint32_t soff = ((((uint32_t)(ks * 4 + t)) ^ asw) << 3);
#pragma unroll
    for (int mt = 0; mt < 2; mt++) {
        lds64(a[mt][0], a[mt][2], arow + (uint32_t)(mt * 2048) + soff);
        lds64(a[mt][1], a[mt][3], arow + (uint32_t)(mt * 2048 + 1024) + soff);
    }
#pragma unroll
    for (int nt = 0; nt < 4; nt++)
        lds64(b[nt][0], b[nt][1], brow + (uint32_t)(nt * 1024) + soff);
}

// ---------------- kernel 2: persistent B-stationary event GEMM ----------------
__global__ void __launch_bounds__(512, 1) k_events(
    const int* __restrict__ nbr_ev, const int* __restrict__ ev_st,
    const int* __restrict__ ev_dt, const int* __restrict__ ev_et,
    const int* __restrict__ ev_sid, const int* __restrict__ ev_did,
    const int* __restrict__ ev_ts, const float* __restrict__ ev_w,
    const float* __restrict__ emb0, const float* __restrict__ emb1,
    const float* __restrict__ w1, const float* __restrict__ b1v)
{
    const uint32_t smb = smaddr(smf);
    const float** srcP = (const float**)(smf + MJ_SRCP);
    const float** dstP = (const float**)(smf + MJ_DSTP);
    int*    relA = (int*)(smf + MJ_REL);
    float*  vmA  = smf + MJ_VM;
    float*  tsA  = smf + MJ_TS;
    float*  wlA  = smf + MJ_WL;
    float2* w1s  = (float2*)(smf + MJ_W1);
    float*  b1s  = smf + MJ_B1;
    float*  rb   = smf + MJ_RB;

    const int tid = threadIdx.x;
    const int wid = tid >> 5, lane = tid & 31;
    const int wm = wid >> 2, wn = wid & 3;      // 4x4 warp grid, tile 32x32
    const int g = lane >> 2, t = lane & 3;
    const int half = blockIdx.x & 1;

    // ---- one-time: resident B half (8 chunks x 128 rows), tables ----
#pragma unroll
    for (int i = 0; i < 16; i++) {
        int task = tid + i * 512;                // 8192 tasks of 16B
        const char* src = (const char*)g_Bwh
            + ((size_t)((task >> 10) * 2048 + (half << 10) + (task & 1023)) << 4);
        cpa16(smb + (uint32_t)EV_B + (uint32_t)task * 16u, src);
    }
    CP_COMMIT();
#pragma unroll
    for (int i = 0; i < 4; i++) {
        int idx = tid + i * 512;                 // 2048 rb entries
        rb[idx] = g_relb2[(idx >> 7) * 256 + half * 128 + (idx & 127)];
    }
    if (tid < 256) {
        w1s[tid] = make_float2(w1[tid * 2], w1[tid * 2 + 1]);
        b1s[tid] = b1v[tid];
    }
    CP_WAIT(0);
    __syncthreads();

    const int frow = tid >> 2, fks = tid & 3;    // A-fill task: row, kstep

    const uint32_t asw  = ((uint32_t)(g & 3)) << 2;
    const uint32_t arow0 = smb + (uint32_t)EV_A + (uint32_t)((wm * 32 + g) * 128);
    const uint32_t brow0 = smb + (uint32_t)EV_B + (uint32_t)((wn * 32 + g) * 128);
    const uint32_t fdst0 = smb + (uint32_t)EV_A + (uint32_t)(frow * 128)
                         + (((uint32_t)(fks * 4) ^ ((frow & 3) << 2)) << 3);

    for (int job = blockIdx.x >> 1; job < NJOB; job += NSM) {
        __syncthreads();                          // protect meta from prior epilogue readers
        if (tid < 128) {
            int e   = job * 128 + tid;
            int raw = nbr_ev[e];
            int v   = raw >= 0;
            int ev  = v ? raw : 0;
            long sid = ev_sid[ev], did = ev_did[ev];
            srcP[tid] = (ev_st[ev] == 0 ? emb0 : emb1) + sid * EMB;
            dstP[tid] = (ev_dt[ev] == 0 ? emb0 : emb1) + did * EMB;
            relA[tid] = ev_et[ev];
            vmA[tid]  = v ? 1.0f : 0.0f;
            tsA[tid]  = (float)ev_ts[ev] / 1000000.0f;
            wlA[tid]  = log1pf(ev_w[ev]);
        }
        __syncthreads();

        float acc[2][4][4];
#pragma unroll
        for (int mt = 0; mt < 2; mt++)
#pragma unroll
            for (int nt = 0; nt < 4; nt++)
#pragma unroll
                for (int r = 0; r < 4; r++) acc[mt][nt][r] = 0.0f;

        float4 f[4];
        {   // LDG chunk 0
            const float* src = srcP[frow] + fks * 16;
#pragma unroll
            for (int q = 0; q < 4; q++) f[q] = ((const float4*)src)[q];
        }

#pragma unroll
        for (int kc = 0; kc < 8; kc++) {
            const uint32_t abuf = (uint32_t)((kc & 1) * 16384);
            // ---- STS chunk kc ----
            if (kc < 4) {
                uint32_t h[8];
                cvt_perm(f, h);
                sts128(fdst0 + abuf, h[0], h[1], h[2], h[3]);
                sts128(fdst0 + abuf + 16, h[4], h[5], h[6], h[7]);
            } else {
                int cb = ((kc - 4) << 6) + fks * 16;
                float tsv = tsA[frow], wlv = wlA[frow];
                uint32_t h[8];
#pragma unroll
                for (int p = 0; p < 8; p++) {
                    int j = (p >> 1) + ((p & 1) << 2);
                    int c0 = cb + 2 * j;
                    float2 wa = w1s[c0], wb = w1s[c0 + 1];
                    float v0 = fmaxf(tsv * wa.x + wlv * wa.y + b1s[c0], 0.0f);
                    float v1 = fmaxf(tsv * wb.x + wlv * wb.y + b1s[c0 + 1], 0.0f);
                    h[p] = h2u(__floats2half2_rn(v0, v1));
                }
                sts128(fdst0 + abuf, h[0], h[1], h[2], h[3]);
                sts128(fdst0 + abuf + 16, h[4], h[5], h[6], h[7]);
            }
            __syncthreads();
            // ---- early LDG for next emb chunk (latency hidden under MMA) ----
            if (kc < 3) {
                const float* src = (kc < 1 ? srcP[frow] : dstP[frow])
                                 + (((kc + 1) & 1) << 6) + fks * 16;
#pragma unroll
                for (int q = 0; q < 4; q++) f[q] = ((const float4*)src)[q];
            }
            // ---- MMA chunk kc (kstep-pipelined) ----
            {
                const uint32_t aB = arow0 + abuf;
                const uint32_t bB = brow0 + (uint32_t)(kc * 16384);
                uint32_t a[2][2][4], b[2][4][2];
                frag32(aB, bB, asw, t, 0, a[0], b[0]);
#pragma unroll
                for (int ks = 0; ks < 4; ks++) {
                    const int cur = ks & 1;
                    if (ks < 3) frag32(aB, bB, asw, t, ks + 1, a[cur ^ 1], b[cur ^ 1]);
#pragma unroll
                    for (int nt = 0; nt < 4; nt++) {
                        mma16(acc[0][nt], a[cur][0], b[cur][nt][0], b[cur][nt][1]);
                        mma16(acc[1][nt], a[cur][1], b[cur][nt][0], b[cur][nt][1]);
                    }
                }
            }
        }

        // ---- epilogue: +relb2, relu, mask, mean(16) -> g_neighh ----
#pragma unroll
        for (int mt = 0; mt < 2; mt++) {
            int eg = wm * 32 + mt * 16 + g, eg8 = eg + 8;
            float vg = vmA[eg], vg8 = vmA[eg8];
            const float* rbg  = rb + relA[eg] * 128;
            const float* rbg8 = rb + relA[eg8] * 128;
            int node = job * 8 + wm * 2 + mt;
#pragma unroll
            for (int nt = 0; nt < 4; nt++) {
                int chf = wn * 32 + nt * 8 + t * 2;         // col within half
                float s0 = fmaxf(acc[mt][nt][0] + rbg[chf], 0.0f) * vg
                         + fmaxf(acc[mt][nt][2] + rbg8[chf], 0.0f) * vg8;
                float s1 = fmaxf(acc[mt][nt][1] + rbg[chf + 1], 0.0f) * vg
                         + fmaxf(acc[mt][nt][3] + rbg8[chf + 1], 0.0f) * vg8;
                s0 += __shfl_xor_sync(0xFFFFFFFFu, s0, 4);
                s0 += __shfl_xor_sync(0xFFFFFFFFu, s0, 8);
                s0 += __shfl_xor_sync(0xFFFFFFFFu, s0, 16);
                s1 += __shfl_xor_sync(0xFFFFFFFFu, s1, 4);
                s1 += __shfl_xor_sync(0xFFFFFFFFu, s1, 8);
                s1 += __shfl_xor_sync(0xFFFFFFFFu, s1, 16);
                if (g == 0) {
                    int colg = half * 128 + chf;
                    int q = colg >> 1, c64 = q >> 5, j5 = q & 31;
                    int ks = j5 >> 3, j = j5 & 7, p = 2 * (j & 3) + (j >> 2);
                    *(__half2*)(g_neighh + node * 256 + c64 * 64 + ks * 16 + p * 2) =
                        __floats2half2_rn(s0 * 0.0625f, s1 * 0.0625f);
                }
            }
        }
    }
}

// ---------------- kernel 3: out = relu(self_e @ Wself^T + neigh @ Wneigh^T) ----------------
DEVI void fill_emb_kstep(uint32_t aB, const float* src, int row, int ks) {
    float4 f[4];
#pragma unroll
    for (int q = 0; q < 4; q++) f[q] = ((const float4*)src)[q];
    uint32_t h[8];
    cvt_perm(f, h);
    uint32_t dest = aB + (uint32_t)(row * 128) + (((uint32_t)(ks * 4) ^ ((row & 3) << 2)) << 3);
    sts128(dest, h[0], h[1], h[2], h[3]);
    sts128(dest + 16, h[4], h[5], h[6], h[7]);
}

DEVI void frag64(uint32_t arow, uint32_t brow0, uint32_t asw, int t, int ks,
                 uint32_t (&a)[2][4], uint32_t (&b)[8][2]) {
    const uint32_t soff = ((((uint32_t)(ks * 4 + t)) ^ asw) << 3);
#pragma unroll
    for (int mt = 0; mt < 2; mt++) {
        lds64(a[mt][0], a[mt][2], arow + (uint32_t)(mt * 2048) + soff);
        lds64(a[mt][1], a[mt][3], arow + (uint32_t)(mt * 2048 + 1024) + soff);
    }
#pragma unroll
    for (int nt = 0; nt < 8; nt++)
        lds64(b[nt][0], b[nt][1], brow0 + (uint32_t)(nt * 1024) + soff);
}

__global__ void __launch_bounds__(512) k_final(
    const int* __restrict__ node_ids, const float* __restrict__ emb0,
    float* __restrict__ out)
{
    const uint32_t smb = smaddr(smf);
    const float** selfP = (const float**)(smf + MI);

    const int tid = threadIdx.x;
    const int wid = tid >> 5, lane = tid & 31;
    const int wm = wid >> 2, wn = wid & 3;
    const int g = lane >> 2, t = lane & 3;

    if (tid < 128) {
        long nid = node_ids[blockIdx.x * 128 + tid];
        selfP[tid] = emb0 + nid * EMB;
    }
    __syncthreads();

    const int frow = tid >> 2, fks = tid & 3;

    auto load_chunk = [&](int kc, int s) {
        const uint32_t base = smb + (uint32_t)(s * STG);
#pragma unroll
        for (int i = 0; i < 4; i++) {
            int task = tid + i * 512;
            cpa16(base + (uint32_t)A_BYT + (uint32_t)task * 16u,
                  (const char*)g_Bw2h + (size_t)kc * CH_BYT + task * 16);
        }
        if (kc < 2) {
            const float* src = selfP[frow] + (kc << 6) + fks * 16;
            fill_emb_kstep(base, src, frow, fks);
        } else {
#pragma unroll
            for (int i = 0; i < 2; i++) {
                int task = tid + i * 512, row = task >> 3, c = task & 7;
                const __half* src = g_neighh + (size_t)(blockIdx.x * 128 + row) * 256
                                  + ((kc - 2) << 6) + c * 8;
                uint32_t dest = base + (uint32_t)(row * 128)
                              + (((uint32_t)c ^ ((row & 3) << 1)) << 4);
                cpa16(dest, src);
            }
        }
    };

    float acc[2][8][4];
#pragma unroll
    for (int mt = 0; mt < 2; mt++)
#pragma unroll
        for (int nt = 0; nt < 8; nt++)
#pragma unroll
            for (int r = 0; r < 4; r++) acc[mt][nt][r] = 0.0f;

    load_chunk(0, 0); CP_COMMIT();
    load_chunk(1, 1); CP_COMMIT();
    for (int kc = 0; kc < 6; kc++) {
        int s = kc % 3;
        if (kc == 5) { CP_WAIT(0); } else { CP_WAIT(1); }
        __syncthreads();
        if (kc < 4) { load_chunk(kc + 2, (kc + 2) % 3); CP_COMMIT(); }
        // MMA: warp tile 32x64
        const uint32_t asw  = ((uint32_t)(g & 3)) << 2;
        const uint32_t arow = smb + (uint32_t)(s * STG) + (uint32_t)((wm * 32 + g) * 128);
        const uint32_t brow = smb + (uint32_t)(s * STG + A_BYT) + (uint32_t)((wn * 64 + g) * 128);
        uint32_t a[2][2][4], b[2][8][2];
        frag64(arow, brow, asw, t, 0, a[0], b[0]);
#pragma unroll
        for (int ks = 0; ks < 4; ks++) {
            const int cur = ks & 1;
            if (ks < 3) frag64(arow, brow, asw, t, ks + 1, a[cur ^ 1], b[cur ^ 1]);
#pragma unroll
            for (int nt = 0; nt < 8; nt++) {
                mma16(acc[0][nt], a[cur][0], b[cur][nt][0], b[cur][nt][1]);
                mma16(acc[1][nt], a[cur][1], b[cur][nt][0], b[cur][nt][1]);
            }
        }
    }

#pragma unroll
    for (int mt = 0; mt < 2; mt++) {
        int row0 = blockIdx.x * 128 + wm * 32 + mt * 16;
#pragma unroll
        for (int nt = 0; nt < 8; nt++) {
            int col = wn * 64 + nt * 8 + t * 2;
            *(float2*)(out + (long)(row0 + g) * 256 + col) =
                make_float2(fmaxf(acc[mt][nt][0], 0.0f), fmaxf(acc[mt][nt][1], 0.0f));
            *(float2*)(out + (long)(row0 + g + 8) * 256 + col) =
                make_float2(fmaxf(acc[mt][nt][2], 0.0f), fmaxf(acc[mt][nt][3], 0.0f));
        }
    }
}

extern "C" void kernel_launch(void* const* d_in, const int* in_sizes, int n_in,
                              void* d_out, int out_size) {
    const int*   node_ids = (const int*)d_in[0];
    const int*   nbr_ev   = (const int*)d_in[1];
    const int*   ev_st    = (const int*)d_in[2];
    const int*   ev_dt    = (const int*)d_in[3];
    const int*   ev_et    = (const int*)d_in[4];
    const int*   ev_sid   = (const int*)d_in[5];
    const int*   ev_did   = (const int*)d_in[6];
    const int*   ev_ts    = (const int*)d_in[7];
    const float* ev_w     = (const float*)d_in[8];
    const float* emb0     = (const float*)d_in[9];
    const float* emb1     = (const float*)d_in[10];
    const float* edge_emb = (const float*)d_in[11];
    const float* edge_lin = (const float*)d_in[12];
    const float* mlp_w1   = (const float*)d_in[13];
    const float* mlp_b1   = (const float*)d_in[14];
    const float* mlp_w2   = (const float*)d_in[15];
    const float* mlp_b2   = (const float*)d_in[16];
    const float* ev_src_w = (const float*)d_in[17];
    const float* ev_dst_w = (const float*)d_in[18];
    const float* self_w   = (const float*)d_in[19];
    const float* neigh_w  = (const float*)d_in[20];
    float* out = (float*)d_out;

    cudaFuncSetAttribute(k_events, cudaFuncAttributeMaxDynamicSharedMemorySize, SMEM_EV);
    cudaFuncSetAttribute(k_final,  cudaFuncAttributeMaxDynamicSharedMemorySize, SMEM_FI);

    k_prep<<<896, 256>>>(ev_src_w, ev_dst_w, mlp_w2, self_w, neigh_w);
    k_relproj<<<16, 256>>>(edge_emb, edge_lin, mlp_b2);
    k_events<<<2 * NSM, 512, SMEM_EV>>>(nbr_ev, ev_st, ev_dt, ev_et, ev_sid, ev_did,
                                        ev_ts, ev_w, emb0, emb1, mlp_w1, mlp_b1);
    k_final<<<BN / 128, 512, SMEM_FI>>>(node_ids, emb0, out);
}